// round 2
// baseline (speedup 1.0000x reference)
#include <cuda_runtime.h>
#include <stdint.h>

// ---------------------------------------------------------------------------
// TiledFeaturesMap: B=4, N=2048, C=512, FS=1, T_SZ=9, T_STEP=6, T_CUT=2
// Output: float32 [ f_ns (K) | f_tiles (K*512*81) ], K = out_size/41473.
// ---------------------------------------------------------------------------

#define NB   4
#define NP   2048
#define NC   512
#define TSZ  9
#define CELLS (TSZ*TSZ)          // 81
#define TILE_ELEMS (NC*CELLS)    // 41472
#define KMAX 2048
#define CHUNK 128                // channels staged per pass
#define NCHUNK (NC/CHUNK)        // 4
#define CHUNK_ELEMS (CHUNK*CELLS) // 10368 (divisible by 4)

__device__ short g_pts[NB * NP];        // packed y*128+x (raw coords)
__device__ int   g_bounds[NB * 4];      // ymin,ymax,xmin,xmax per batch
__device__ int   g_slot_batch[KMAX];
__device__ int   g_cnt[KMAX];
__device__ int   g_list[KMAX * CELLS];  // (cell<<16)|n entries, g_cnt[s] used

// ---------------------------------------------------------------------------
// prep: 4 blocks (one per batch) x 256. Coord load + min/max + pack.
// ---------------------------------------------------------------------------
__global__ __launch_bounds__(256) void prep_kernel(const void* __restrict__ ys_raw,
                                                   const void* __restrict__ xs_raw)
{
    const int b = blockIdx.x;
    const int tid = threadIdx.x;
    __shared__ int s_bad, s_ymin, s_ymax, s_xmin, s_xmax;
    if (tid == 0) { s_bad = 0; s_ymin = 1 << 30; s_ymax = -1; s_xmin = 1 << 30; s_xmax = -1; }
    __syncthreads();

    // dtype detect on this batch's 16KB region (int64: odd 32-bit words == 0)
    {
        const int* yw = (const int*)ys_raw;
        const int* xw = (const int*)xs_raw;
        int bad = 0;
        for (int i = b * 4096 + 1 + 2 * tid; i < (b + 1) * 4096; i += 512)
            bad |= yw[i] | xw[i];
        bad = __reduce_or_sync(0xffffffffu, bad);
        if ((tid & 31) == 0 && bad) atomicOr(&s_bad, 1);
    }
    __syncthreads();
    const bool is64 = (s_bad == 0);

    for (int i = tid; i < NP; i += 256) {
        const int gidx = b * NP + i;
        int y, x;
        if (is64) {
            y = (int)((const long long*)ys_raw)[gidx];
            x = (int)((const long long*)xs_raw)[gidx];
        } else {
            y = ((const int*)ys_raw)[gidx];
            x = ((const int*)xs_raw)[gidx];
        }
        g_pts[gidx] = (short)(y * 128 + x);
        const int wymin = __reduce_min_sync(0xffffffffu, y);
        const int wymax = __reduce_max_sync(0xffffffffu, y);
        const int wxmin = __reduce_min_sync(0xffffffffu, x);
        const int wxmax = __reduce_max_sync(0xffffffffu, x);
        if ((tid & 31) == 0) {
            atomicMin(&s_ymin, wymin); atomicMax(&s_ymax, wymax);
            atomicMin(&s_xmin, wxmin); atomicMax(&s_xmax, wxmax);
        }
    }
    __syncthreads();
    if (tid == 0) {
        g_bounds[b * 4 + 0] = s_ymin; g_bounds[b * 4 + 1] = s_ymax;
        g_bounds[b * 4 + 2] = s_xmin; g_bounds[b * 4 + 3] = s_xmax;
    }
}

// ---------------------------------------------------------------------------
// build: 1 block x 1024. Mask -> scan -> slot map -> compact per-slot lists.
// ---------------------------------------------------------------------------
__global__ __launch_bounds__(1024) void build_kernel()
{
    __shared__ short s_yx[NB * NP];          // shifted packed coords
    __shared__ unsigned char s_mask[NB * 512];
    __shared__ int s_scan[2048];
    __shared__ int s_cnt[2048];
    __shared__ int s_wsum[32];
    __shared__ int s_ymin[NB], s_xmin[NB], s_nH[NB], s_nW[NB], s_base[NB + 1];
    __shared__ int s_half0;

    const int tid = threadIdx.x;

    if (tid < NB) {
        const int ymin = g_bounds[tid * 4 + 0], ymax = g_bounds[tid * 4 + 1];
        const int xmin = g_bounds[tid * 4 + 2], xmax = g_bounds[tid * 4 + 3];
        s_ymin[tid] = ymin; s_xmin[tid] = xmin;
        s_nH[tid] = (ymax - ymin + 1) / 6 + 1;
        s_nW[tid] = (xmax - xmin + 1) / 6 + 1;
    }
    for (int i = tid; i < NB * 128; i += 1024) ((int*)s_mask)[i] = 0;
    __syncthreads();
    if (tid == 0) {
        s_base[0] = 0;
        for (int b = 0; b < NB; b++) s_base[b + 1] = s_base[b] + s_nH[b] * s_nW[b];
    }
    __syncthreads();

    // shift coords + mark center occupancy (center 5x5 of stride-6 tile:
    // r=y%6: 1 -> none; 0 -> tile y/6-1; 2..5 -> tile y/6)
    for (int idx = tid; idx < NB * NP; idx += 1024) {
        const int b = idx >> 11;
        const int v = g_pts[idx];
        const int y = (v >> 7) - s_ymin[b];
        const int x = (v & 127) - s_xmin[b];
        s_yx[idx] = (short)(y * 128 + x);
        const int qy = y / 6, ry = y - 6 * qy;
        const int qx = x / 6, rx = x - 6 * qx;
        const int cy = (ry == 1) ? -1 : ((ry == 0) ? qy - 1 : qy);
        const int cx = (rx == 1) ? -1 : ((rx == 0) ? qx - 1 : qx);
        if (cy >= 0 && cx >= 0)
            s_mask[b * 512 + cy * s_nW[b] + cx] = 1;
    }
    __syncthreads();

    const int Ttot = s_base[NB];   // <= 4*21*21 = 1764

    // selection flags in tile order
    for (int t = tid; t < 2048; t += 1024) {
        int sel = 0;
        if (t < Ttot) {
            const int b = (t >= s_base[3]) ? 3 : (t >= s_base[2]) ? 2
                        : (t >= s_base[1]) ? 1 : 0;
            sel = s_mask[b * 512 + (t - s_base[b])];
        }
        s_scan[t] = sel;
    }
    __syncthreads();

    // inclusive scan of 2048 flags: two 1024-halves via warp shuffles
    {
        const int w = tid >> 5, lane = tid & 31;
        for (int h = 0; h < 2; h++) {
            int v = s_scan[h * 1024 + tid];
            for (int off = 1; off < 32; off <<= 1) {
                const int t = __shfl_up_sync(0xffffffffu, v, off);
                if (lane >= off) v += t;
            }
            if (lane == 31) s_wsum[w] = v;
            __syncthreads();
            if (w == 0) {
                int sv = s_wsum[lane];
                for (int off = 1; off < 32; off <<= 1) {
                    const int t = __shfl_up_sync(0xffffffffu, sv, off);
                    if (lane >= off) sv += t;
                }
                s_wsum[lane] = sv;
            }
            __syncthreads();
            const int add = (w > 0 ? s_wsum[w - 1] : 0) + (h ? s_half0 : 0);
            s_scan[h * 1024 + tid] = v + add;
            if (h == 0 && tid == 0) s_half0 = s_wsum[31];
            __syncthreads();
        }
    }

    // scan -> slot_of_tile in place; record slot batch; zero counters
    for (int t = tid; t < 2048; t += 1024) {
        s_cnt[t] = 0;
        int slotv = -1;
        if (t < Ttot) {
            const int b = (t >= s_base[3]) ? 3 : (t >= s_base[2]) ? 2
                        : (t >= s_base[1]) ? 1 : 0;
            if (s_mask[b * 512 + (t - s_base[b])]) {
                slotv = s_scan[t] - 1;
                g_slot_batch[slotv] = b;
            }
        }
        __syncthreads();
        s_scan[t] = slotv;
    }
    __syncthreads();

    // scatter points into compact per-slot lists
    for (int idx = tid; idx < NB * NP; idx += 1024) {
        const int b = idx >> 11;
        const int v = s_yx[idx];
        const int y = v >> 7, x = v & 127;
        const int nW = s_nW[b], nH = s_nH[b];
        const int ilo = (y > 8) ? (y - 3) / 6 : 0;
        int       ihi = y / 6;  if (ihi > nH - 1) ihi = nH - 1;
        const int jlo = (x > 8) ? (x - 3) / 6 : 0;
        int       jhi = x / 6;  if (jhi > nW - 1) jhi = nW - 1;
        const int n = idx & (NP - 1);
        for (int i = ilo; i <= ihi; i++)
            for (int j = jlo; j <= jhi; j++) {
                const int slot = s_scan[s_base[b] + i * nW + j];
                if (slot >= 0) {
                    const int pos = atomicAdd(&s_cnt[slot], 1);
                    g_list[slot * CELLS + pos] = ((y - i * 6) * TSZ + (x - j * 6)) << 16 | n;
                }
            }
    }
    __syncthreads();
    for (int t = tid; t < 2048; t += 1024) g_cnt[t] = s_cnt[t];
}

// ---------------------------------------------------------------------------
// tiles: 1 block per selected tile. Stage occupied points' channels into smem
// (coalesced gmem reads), then emit float4 stores reading from smem.
// ---------------------------------------------------------------------------
__global__ __launch_bounds__(256) void tiles_kernel(const float* __restrict__ features,
                                                    float* __restrict__ out,
                                                    int ns_count)
{
    const int s = blockIdx.x;
    const int tid = threadIdx.x;

    __shared__ float sbuf[CELLS * (CHUNK + 1)];   // 81 x 129 floats
    __shared__ int   cmap[CELLS];                  // cell -> point-list idx / -1
    __shared__ short plist[CELLS];
    __shared__ int   s_meta[2];                    // cnt, batch

    if (tid == 0) {
        s_meta[0] = g_cnt[s];
        const int b = g_slot_batch[s];
        s_meta[1] = b;
        if (ns_count > 0) out[s] = (float)b;       // f_ns
    }
    if (tid < CELLS) cmap[tid] = -1;
    __syncthreads();
    const int cnt = s_meta[0];
    if (tid < cnt) {
        const int e = g_list[s * CELLS + tid];
        plist[tid] = (short)(e & 0xffff);
        cmap[e >> 16] = tid;
    }
    const float* __restrict__ fb = features + (size_t)s_meta[1] * (NP * NC);
    const size_t base = (size_t)ns_count + (size_t)s * TILE_ELEMS;
    const int head = (int)((4u - ((unsigned)base & 3u)) & 3u);   // same all chunks
    const int nb4  = (CHUNK_ELEMS - head) >> 2;
    const int tail = (CHUNK_ELEMS - head) & 3;

    for (int chunk = 0; chunk < NCHUNK; chunk++) {
        const int c0 = chunk * CHUNK;
        __syncthreads();                           // prev write phase done / maps ready
        // stage: coalesced rows of CHUNK floats per occupied point
        for (int i = tid; i < cnt * CHUNK; i += 256) {
            const int p = i >> 7, c = i & (CHUNK - 1);
            sbuf[p * (CHUNK + 1) + c] = fb[(int)plist[p] * NC + c0 + c];
        }
        __syncthreads();

        float* __restrict__ ochunk = out + base + (size_t)c0 * CELLS;

        for (int lin = tid; lin < head; lin += 256) {
            const unsigned cl = (unsigned)lin / 81u;
            const int cell = lin - (int)(cl * 81u);
            const int idx = cmap[cell];
            ochunk[lin] = (idx >= 0) ? sbuf[idx * (CHUNK + 1) + cl] : 0.0f;
        }
        for (int k = tid; k < nb4; k += 256) {
            const int lin = head + (k << 2);
            const unsigned cl0 = (unsigned)lin / 81u;
            const int cell0 = lin - (int)(cl0 * 81u);
            float4 v; float* pv = (float*)&v;
#pragma unroll
            for (int e = 0; e < 4; e++) {
                int cc = cell0 + e;
                unsigned cl = cl0;
                if (cc >= CELLS) { cc -= CELLS; cl++; }
                const int idx = cmap[cc];
                pv[e] = (idx >= 0) ? sbuf[idx * (CHUNK + 1) + cl] : 0.0f;
            }
            *(float4*)(ochunk + lin) = v;
        }
        for (int k = tid; k < tail; k += 256) {
            const int lin = head + (nb4 << 2) + k;
            const unsigned cl = (unsigned)lin / 81u;
            const int cell = lin - (int)(cl * 81u);
            const int idx = cmap[cell];
            ochunk[lin] = (idx >= 0) ? sbuf[idx * (CHUNK + 1) + cl] : 0.0f;
        }
    }
}

// ---------------------------------------------------------------------------
extern "C" void kernel_launch(void* const* d_in, const int* in_sizes, int n_in,
                              void* d_out, int out_size)
{
    int fi = 0;
    for (int i = 0; i < n_in; i++)
        if (in_sizes[i] == NB * NP * NC) fi = i;
    const float* features = (const float*)d_in[fi];
    const void* ys = nullptr;
    const void* xs = nullptr;
    for (int i = 0; i < n_in; i++) {
        if (i == fi) continue;
        if (!ys) ys = d_in[i];
        else if (!xs) xs = d_in[i];
    }

    prep_kernel<<<NB, 256>>>(ys, xs);
    build_kernel<<<1, 1024>>>();

    int K, ns_count;
    if (out_size % (TILE_ELEMS + 1) == 0) {
        K = out_size / (TILE_ELEMS + 1);
        ns_count = K;
    } else {
        K = out_size / TILE_ELEMS;
        ns_count = 0;
    }
    if (K <= 0) return;
    if (K > KMAX) K = KMAX;

    tiles_kernel<<<K, 256>>>(features, (float*)d_out, ns_count);
}

// round 3
// speedup vs baseline: 1.6080x; 1.6080x over previous
#include <cuda_runtime.h>
#include <stdint.h>

// ---------------------------------------------------------------------------
// TiledFeaturesMap: B=4, N=2048, C=512, FS=1, T_SZ=9, T_STEP=6, T_CUT=2
// Output: float32 [ f_ns (K) | f_tiles (K*512*81) ], K = out_size/41473.
// ---------------------------------------------------------------------------

#define NB 4
#define NP 2048
#define NC 512
#define TSZ 9
#define CELLS 81
#define TILE_ELEMS 41472
#define SLOTMAX 512            // per-batch selected-tile capacity (<= 441 used)

__device__ int g_selcnt[NB];
__device__ int g_cnt[NB * SLOTMAX];
__device__ int g_list[NB * SLOTMAX * CELLS];   // (cell<<16)|n

// ---------------------------------------------------------------------------
// setup: 4 blocks (one per batch) x 512 threads. Fully independent per batch:
// coord load -> min/max -> center-occupancy mask -> local scan -> slot ids ->
// scatter points into compact per-slot lists.
// ---------------------------------------------------------------------------
__global__ __launch_bounds__(512) void setup_kernel(const void* __restrict__ ys_raw,
                                                    const void* __restrict__ xs_raw)
{
    const int b = blockIdx.x;
    const int tid = threadIdx.x;

    __shared__ int s_bad, s_ymin, s_ymax, s_xmin, s_xmax;
    __shared__ unsigned char s_mask[512];
    __shared__ short s_slot[512];
    __shared__ int s_cnt[512];
    __shared__ int s_ws[16];
    __shared__ int s_nH, s_nW, s_T;

    if (tid == 0) { s_bad = 0; s_ymin = 1 << 30; s_ymax = -1; s_xmin = 1 << 30; s_xmax = -1; }
    s_mask[tid] = 0;
    s_cnt[tid] = 0;
    __syncthreads();

    // dtype detect on this batch's region (int64 LE: odd 32-bit words all 0)
    {
        const int* yw = (const int*)ys_raw;
        const int* xw = (const int*)xs_raw;
        int bad = 0;
        for (int i = b * 2 * NP + 1 + 2 * tid; i < (b + 1) * 2 * NP; i += 1024)
            bad |= yw[i] | xw[i];
        bad = __reduce_or_sync(0xffffffffu, bad);
        if ((tid & 31) == 0 && bad) atomicOr(&s_bad, 1);
    }
    __syncthreads();
    const bool is64 = (s_bad == 0);

    // load 4 points per thread into registers
    int py[4], px[4];
#pragma unroll
    for (int j = 0; j < 4; j++) {
        const int idx = b * NP + tid + j * 512;
        if (is64) {
            py[j] = (int)((const long long*)ys_raw)[idx];
            px[j] = (int)((const long long*)xs_raw)[idx];
        } else {
            py[j] = ((const int*)ys_raw)[idx];
            px[j] = ((const int*)xs_raw)[idx];
        }
    }
    {
        int ymn = py[0], ymx = py[0], xmn = px[0], xmx = px[0];
#pragma unroll
        for (int j = 1; j < 4; j++) {
            ymn = min(ymn, py[j]); ymx = max(ymx, py[j]);
            xmn = min(xmn, px[j]); xmx = max(xmx, px[j]);
        }
        ymn = __reduce_min_sync(0xffffffffu, ymn);
        ymx = __reduce_max_sync(0xffffffffu, ymx);
        xmn = __reduce_min_sync(0xffffffffu, xmn);
        xmx = __reduce_max_sync(0xffffffffu, xmx);
        if ((tid & 31) == 0) {
            atomicMin(&s_ymin, ymn); atomicMax(&s_ymax, ymx);
            atomicMin(&s_xmin, xmn); atomicMax(&s_xmax, xmx);
        }
    }
    __syncthreads();
    if (tid == 0) {
        s_nH = (s_ymax - s_ymin + 1) / 6 + 1;
        s_nW = (s_xmax - s_xmin + 1) / 6 + 1;
        s_T = s_nH * s_nW;
    }
    __syncthreads();
    const int nH = s_nH, nW = s_nW, T = s_T;
    const int ymin = s_ymin, xmin = s_xmin;

    // shift + mark center occupancy (center 5x5 of stride-6 tile:
    // r%6: 1 -> none; 0 -> tile q-1; 2..5 -> tile q)
#pragma unroll
    for (int j = 0; j < 4; j++) {
        const int y = py[j] - ymin, x = px[j] - xmin;
        py[j] = y; px[j] = x;
        const int qy = y / 6, ry = y - 6 * qy;
        const int qx = x / 6, rx = x - 6 * qx;
        const int cy = (ry == 1) ? -1 : ((ry == 0) ? qy - 1 : qy);
        const int cx = (rx == 1) ? -1 : ((rx == 0) ? qx - 1 : qx);
        if (cy >= 0 && cx >= 0) s_mask[cy * nW + cx] = 1;
    }
    __syncthreads();

    // inclusive scan of selection flags over T (<=441) entries
    {
        const int w = tid >> 5, lane = tid & 31;
        const int f = (tid < T) ? (int)s_mask[tid] : 0;
        int v = f;
        for (int off = 1; off < 32; off <<= 1) {
            const int t = __shfl_up_sync(0xffffffffu, v, off);
            if (lane >= off) v += t;
        }
        if (lane == 31) s_ws[w] = v;
        __syncthreads();
        if (w == 0 && lane < 16) {
            int sv = s_ws[lane];
            for (int off = 1; off < 16; off <<= 1) {
                const int t = __shfl_up_sync(0xffffu, sv, off);
                if (lane >= off) sv += t;
            }
            s_ws[lane] = sv;
        }
        __syncthreads();
        const int pre = (w > 0) ? s_ws[w - 1] : 0;
        s_slot[tid] = (short)(f ? (pre + v - 1) : -1);
        if (tid == 0) g_selcnt[b] = s_ws[15];
    }
    __syncthreads();

    // scatter points into per-slot lists (each point covers <=2x2 windows)
#pragma unroll
    for (int j = 0; j < 4; j++) {
        const int y = py[j], x = px[j];
        const int n = tid + j * 512;
        const int ilo = (y > 8) ? (y - 3) / 6 : 0;
        int       ihi = y / 6;  if (ihi > nH - 1) ihi = nH - 1;
        const int jlo = (x > 8) ? (x - 3) / 6 : 0;
        int       jhi = x / 6;  if (jhi > nW - 1) jhi = nW - 1;
        for (int i = ilo; i <= ihi; i++)
            for (int jj = jlo; jj <= jhi; jj++) {
                const int slot = s_slot[i * nW + jj];
                if (slot >= 0) {
                    const int pos = atomicAdd(&s_cnt[slot], 1);
                    g_list[(b * SLOTMAX + slot) * CELLS + pos] =
                        ((y - i * 6) * TSZ + (x - jj * 6)) << 16 | n;
                }
            }
    }
    __syncthreads();
    g_cnt[b * SLOTMAX + tid] = s_cnt[tid];
}

// ---------------------------------------------------------------------------
// tiles: one block per selected tile. Hot loop has no div/mod; streaming
// float4 stores; sparse gathers from L2-resident features.
// ---------------------------------------------------------------------------
__global__ __launch_bounds__(256) void tiles_kernel(const float* __restrict__ features,
                                                    float* __restrict__ out,
                                                    int ns_count, int head)
{
    const int s = blockIdx.x;
    const int tid = threadIdx.x;

    __shared__ short s_n[CELLS];     // cell -> point index, or -1
    __shared__ int s_info[3];        // b, local, cnt

    if (tid < CELLS) s_n[tid] = -1;
    if (tid == 0) {
        const int c0 = g_selcnt[0], c1 = g_selcnt[1], c2 = g_selcnt[2];
        int b, local = s;
        if (s < c0)                 { b = 0; }
        else if (s < c0 + c1)       { b = 1; local = s - c0; }
        else if (s < c0 + c1 + c2)  { b = 2; local = s - c0 - c1; }
        else                        { b = 3; local = s - c0 - c1 - c2; }
        s_info[0] = b; s_info[1] = local;
        s_info[2] = g_cnt[b * SLOTMAX + local];
        if (ns_count > 0) out[s] = (float)b;          // f_ns
    }
    __syncthreads();
    const int b = s_info[0], local = s_info[1], cnt = s_info[2];
    if (tid < cnt) {
        const int e = g_list[(b * SLOTMAX + local) * CELLS + tid];
        s_n[e >> 16] = (short)(e & 0xffff);
    }
    __syncthreads();

    const float* __restrict__ fb = features + (size_t)b * (NP * NC);
    float* __restrict__ obase = out + (size_t)ns_count + (size_t)s * TILE_ELEMS;

    // head scalars (lin < head <= 3 => channel 0, cell = lin)
    if (tid < head) {
        const int n = s_n[tid];
        obase[tid] = (n >= 0) ? fb[n * NC] : 0.0f;
    }

    const int nb4 = (TILE_ELEMS - head) >> 2;
    const int tail = (TILE_ELEMS - head) & 3;

    int lin = head + tid * 4;
    unsigned cl = (unsigned)lin / 81u;            // one div per thread
    int cell = lin - (int)(cl * 81u);

#pragma unroll 2
    for (int k = tid; k < nb4; k += 256) {
        float4 v; float* pv = (float*)&v;
        int cc = cell; unsigned ch = cl;
#pragma unroll
        for (int e = 0; e < 4; e++) {
            const int n = s_n[cc];
            pv[e] = (n >= 0) ? __ldg(fb + n * NC + ch) : 0.0f;
            cc++; if (cc == CELLS) { cc = 0; ch++; }
        }
        __stcs((float4*)(obase + lin), v);
        lin += 1024;                               // 256 threads * 4 elems
        cell += 52; cl += 12;                      // 1024 = 12*81 + 52
        if (cell >= CELLS) { cell -= CELLS; cl++; }
    }

    for (int k = tid; k < tail; k += 256) {
        const int l = head + (nb4 << 2) + k;
        const unsigned c2 = (unsigned)l / 81u;
        const int ce = l - (int)(c2 * 81u);
        const int n = s_n[ce];
        obase[l] = (n >= 0) ? fb[n * NC + c2] : 0.0f;
    }
}

// ---------------------------------------------------------------------------
extern "C" void kernel_launch(void* const* d_in, const int* in_sizes, int n_in,
                              void* d_out, int out_size)
{
    int fi = 0;
    for (int i = 0; i < n_in; i++)
        if (in_sizes[i] == NB * NP * NC) fi = i;
    const float* features = (const float*)d_in[fi];
    const void* ys = nullptr;
    const void* xs = nullptr;
    for (int i = 0; i < n_in; i++) {
        if (i == fi) continue;
        if (!ys) ys = d_in[i];
        else if (!xs) xs = d_in[i];
    }

    setup_kernel<<<NB, 512>>>(ys, xs);

    int K, ns_count;
    if (out_size % (TILE_ELEMS + 1) == 0) {
        K = out_size / (TILE_ELEMS + 1);
        ns_count = K;
    } else {
        K = out_size / TILE_ELEMS;
        ns_count = 0;
    }
    if (K <= 0) return;
    if (K > NB * SLOTMAX) K = NB * SLOTMAX;

    const int head = (4 - (ns_count & 3)) & 3;
    tiles_kernel<<<K, 256>>>(features, (float*)d_out, ns_count, head);
}

// round 4
// speedup vs baseline: 1.7921x; 1.1145x over previous
#include <cuda_runtime.h>
#include <stdint.h>

// ---------------------------------------------------------------------------
// TiledFeaturesMap: B=4, N=2048, C=512, FS=1, T_SZ=9, T_STEP=6, T_CUT=2
// Output: float32 [ f_ns (K) | f_tiles (K*512*81) ], K = out_size/41473.
// ---------------------------------------------------------------------------

#define NB 4
#define NP 2048
#define NC 512
#define TSZ 9
#define CELLS 81
#define TILE_ELEMS 41472
#define SLOTMAX 512
#define CHUNK 128                       // channels per staged pass
#define NCHUNK (NC / CHUNK)             // 4
#define CHUNK_ELEMS (CHUNK * CELLS)     // 10368 (multiple of 4)

__device__ int g_selcnt[NB];
__device__ int g_cnt[NB * SLOTMAX];
__device__ int g_list[NB * SLOTMAX * CELLS];   // (cell<<16)|n

// ---------------------------------------------------------------------------
// setup: 4 blocks (one per batch) x 512 threads.
// ---------------------------------------------------------------------------
__global__ __launch_bounds__(512) void setup_kernel(const void* __restrict__ ys_raw,
                                                    const void* __restrict__ xs_raw)
{
    const int b = blockIdx.x;
    const int tid = threadIdx.x;

    __shared__ int s_bad, s_ymin, s_ymax, s_xmin, s_xmax;
    __shared__ unsigned char s_mask[512];
    __shared__ short s_slot[512];
    __shared__ int s_cnt[512];
    __shared__ int s_ws[16];
    __shared__ int s_nH, s_nW, s_T;

    if (tid == 0) { s_bad = 0; s_ymin = 1 << 30; s_ymax = -1; s_xmin = 1 << 30; s_xmax = -1; }
    s_mask[tid] = 0;
    s_cnt[tid] = 0;
    __syncthreads();

    // dtype detect (int64 LE: odd 32-bit words all 0)
    {
        const int* yw = (const int*)ys_raw;
        const int* xw = (const int*)xs_raw;
        int bad = 0;
        for (int i = b * 2 * NP + 1 + 2 * tid; i < (b + 1) * 2 * NP; i += 1024)
            bad |= yw[i] | xw[i];
        bad = __reduce_or_sync(0xffffffffu, bad);
        if ((tid & 31) == 0 && bad) atomicOr(&s_bad, 1);
    }
    __syncthreads();
    const bool is64 = (s_bad == 0);

    int py[4], px[4];
#pragma unroll
    for (int j = 0; j < 4; j++) {
        const int idx = b * NP + tid + j * 512;
        if (is64) {
            py[j] = (int)((const long long*)ys_raw)[idx];
            px[j] = (int)((const long long*)xs_raw)[idx];
        } else {
            py[j] = ((const int*)ys_raw)[idx];
            px[j] = ((const int*)xs_raw)[idx];
        }
    }
    {
        int ymn = py[0], ymx = py[0], xmn = px[0], xmx = px[0];
#pragma unroll
        for (int j = 1; j < 4; j++) {
            ymn = min(ymn, py[j]); ymx = max(ymx, py[j]);
            xmn = min(xmn, px[j]); xmx = max(xmx, px[j]);
        }
        ymn = __reduce_min_sync(0xffffffffu, ymn);
        ymx = __reduce_max_sync(0xffffffffu, ymx);
        xmn = __reduce_min_sync(0xffffffffu, xmn);
        xmx = __reduce_max_sync(0xffffffffu, xmx);
        if ((tid & 31) == 0) {
            atomicMin(&s_ymin, ymn); atomicMax(&s_ymax, ymx);
            atomicMin(&s_xmin, xmn); atomicMax(&s_xmax, xmx);
        }
    }
    __syncthreads();
    if (tid == 0) {
        s_nH = (s_ymax - s_ymin + 1) / 6 + 1;
        s_nW = (s_xmax - s_xmin + 1) / 6 + 1;
        s_T = s_nH * s_nW;
    }
    __syncthreads();
    const int nH = s_nH, nW = s_nW, T = s_T;
    const int ymin = s_ymin, xmin = s_xmin;

    // shift + center occupancy (r%6: 1 -> none; 0 -> tile q-1; 2..5 -> tile q)
#pragma unroll
    for (int j = 0; j < 4; j++) {
        const int y = py[j] - ymin, x = px[j] - xmin;
        py[j] = y; px[j] = x;
        const int qy = y / 6, ry = y - 6 * qy;
        const int qx = x / 6, rx = x - 6 * qx;
        const int cy = (ry == 1) ? -1 : ((ry == 0) ? qy - 1 : qy);
        const int cx = (rx == 1) ? -1 : ((rx == 0) ? qx - 1 : qx);
        if (cy >= 0 && cx >= 0) s_mask[cy * nW + cx] = 1;
    }
    __syncthreads();

    // inclusive scan of flags over T (<=441)
    {
        const int w = tid >> 5, lane = tid & 31;
        const int f = (tid < T) ? (int)s_mask[tid] : 0;
        int v = f;
        for (int off = 1; off < 32; off <<= 1) {
            const int t = __shfl_up_sync(0xffffffffu, v, off);
            if (lane >= off) v += t;
        }
        if (lane == 31) s_ws[w] = v;
        __syncthreads();
        if (w == 0 && lane < 16) {
            int sv = s_ws[lane];
            for (int off = 1; off < 16; off <<= 1) {
                const int t = __shfl_up_sync(0xffffu, sv, off);
                if (lane >= off) sv += t;
            }
            s_ws[lane] = sv;
        }
        __syncthreads();
        const int pre = (w > 0) ? s_ws[w - 1] : 0;
        s_slot[tid] = (short)(f ? (pre + v - 1) : -1);
        if (tid == 0) g_selcnt[b] = s_ws[15];
    }
    __syncthreads();

    // scatter points into per-slot lists (each point covers <=2x2 windows)
#pragma unroll
    for (int j = 0; j < 4; j++) {
        const int y = py[j], x = px[j];
        const int n = tid + j * 512;
        const int ilo = (y > 8) ? (y - 3) / 6 : 0;
        int       ihi = y / 6;  if (ihi > nH - 1) ihi = nH - 1;
        const int jlo = (x > 8) ? (x - 3) / 6 : 0;
        int       jhi = x / 6;  if (jhi > nW - 1) jhi = nW - 1;
        for (int i = ilo; i <= ihi; i++)
            for (int jj = jlo; jj <= jhi; jj++) {
                const int slot = s_slot[i * nW + jj];
                if (slot >= 0) {
                    const int pos = atomicAdd(&s_cnt[slot], 1);
                    g_list[(b * SLOTMAX + slot) * CELLS + pos] =
                        ((y - i * 6) * TSZ + (x - jj * 6)) << 16 | n;
                }
            }
    }
    __syncthreads();
    g_cnt[b * SLOTMAX + tid] = s_cnt[tid];
}

// ---------------------------------------------------------------------------
// tiles: one block per selected tile. Stage a dense [CHUNK][81] chunk in smem
// (coalesced gathers, conflict-free STS), then emit as a pure aligned
// LDS.128 -> STG.128 stream. Unoccupied positions zeroed once per tile.
// ---------------------------------------------------------------------------
__global__ __launch_bounds__(256) void tiles_kernel(const float* __restrict__ features,
                                                    float* __restrict__ out,
                                                    int ns_count, int head)
{
    const int s = blockIdx.x;
    const int tid = threadIdx.x;

    __shared__ float sval[CHUNK_ELEMS + 8];     // +pad for alignment shift
    __shared__ short s_cell[CELLS], s_pn[CELLS];
    __shared__ int s_info[3];                   // b, local, cnt

    if (tid == 0) {
        const int c0 = g_selcnt[0], c1 = g_selcnt[1], c2 = g_selcnt[2];
        int b, local = s;
        if (s < c0)                { b = 0; }
        else if (s < c0 + c1)      { b = 1; local = s - c0; }
        else if (s < c0 + c1 + c2) { b = 2; local = s - c0 - c1; }
        else                       { b = 3; local = s - c0 - c1 - c2; }
        s_info[0] = b; s_info[1] = local;
        s_info[2] = g_cnt[b * SLOTMAX + local];
        if (ns_count > 0) out[s] = (float)b;    // f_ns
    }
    __syncthreads();
    const int b = s_info[0], local = s_info[1], cnt = s_info[2];
    if (tid < cnt) {
        const int e = g_list[(b * SLOTMAX + local) * CELLS + tid];
        s_cell[tid] = (short)(e >> 16);
        s_pn[tid]   = (short)(e & 0xffff);
    }

    // zero staging buffer (whole array incl. pad; float4, 16B-aligned)
    {
        const float4 z = make_float4(0.f, 0.f, 0.f, 0.f);
        for (int i = tid; i < (CHUNK_ELEMS + 8) / 4; i += 256)
            ((float4*)sval)[i] = z;
    }
    __syncthreads();

    const float* __restrict__ fb = features + (size_t)b * (NP * NC);
    float* __restrict__ obase = out + (size_t)ns_count + (size_t)s * TILE_ELEMS;

    const int ofs  = (4 - head) & 3;            // (ofs+head) % 4 == 0
    const int nb4  = (CHUNK_ELEMS - head) >> 2;
    const int tail = (CHUNK_ELEMS - head) & 3;
    const int fill_n = cnt * CHUNK;

    for (int chunk = 0; chunk < NCHUNK; chunk++) {
        const int cbase = chunk * CHUNK;

        // fill: coalesced LDG rows per occupied point; STS stride-81 words
        // (81 mod 32 = 17, odd -> conflict-free)
        for (int i = tid; i < fill_n; i += 256) {
            const int p = i >> 7, c = i & (CHUNK - 1);
            sval[ofs + c * CELLS + (int)s_cell[p]] =
                __ldg(fb + (int)s_pn[p] * NC + cbase + c);
        }
        __syncthreads();

        // emit: pure aligned copy (element j of chunk == sval[ofs + j])
        float* __restrict__ oc = obase + cbase * CELLS;
        for (int j = tid; j < head; j += 256)
            oc[j] = sval[ofs + j];
        for (int k = tid; k < nb4; k += 256) {
            const int j = head + (k << 2);
            const float4 v = *(const float4*)(sval + ofs + j);
            __stcs((float4*)(oc + j), v);
        }
        for (int k = tid; k < tail; k += 256) {
            const int j = head + (nb4 << 2) + k;
            oc[j] = sval[ofs + j];
        }
        __syncthreads();   // emit done before next fill overwrites occupied slots
    }
}

// ---------------------------------------------------------------------------
extern "C" void kernel_launch(void* const* d_in, const int* in_sizes, int n_in,
                              void* d_out, int out_size)
{
    int fi = 0;
    for (int i = 0; i < n_in; i++)
        if (in_sizes[i] == NB * NP * NC) fi = i;
    const float* features = (const float*)d_in[fi];
    const void* ys = nullptr;
    const void* xs = nullptr;
    for (int i = 0; i < n_in; i++) {
        if (i == fi) continue;
        if (!ys) ys = d_in[i];
        else if (!xs) xs = d_in[i];
    }

    setup_kernel<<<NB, 512>>>(ys, xs);

    int K, ns_count;
    if (out_size % (TILE_ELEMS + 1) == 0) {
        K = out_size / (TILE_ELEMS + 1);
        ns_count = K;
    } else {
        K = out_size / TILE_ELEMS;
        ns_count = 0;
    }
    if (K <= 0) return;
    if (K > NB * SLOTMAX) K = NB * SLOTMAX;

    const int head = (4 - (ns_count & 3)) & 3;
    tiles_kernel<<<K, 256>>>(features, (float*)d_out, ns_count, head);
}

// round 6
// speedup vs baseline: 1.8951x; 1.0575x over previous
#include <cuda_runtime.h>
#include <stdint.h>

// ---------------------------------------------------------------------------
// TiledFeaturesMap: B=4, N=2048, C=512, FS=1, T_SZ=9, T_STEP=6, T_CUT=2
// Output: float32 [ f_ns (K) | f_tiles (K*512*81) ], K = out_size/41473.
// ---------------------------------------------------------------------------

#define NB 4
#define NP 2048
#define NC 512
#define TSZ 9
#define CELLS 81
#define TILE_ELEMS 41472
#define SLOTMAX 512
#define CHUNK 64                        // channels per block
#define NCHUNK (NC / CHUNK)             // 8
#define CHUNK_ELEMS (CHUNK * CELLS)     // 5184 (multiple of 4)

__device__ int g_selcnt[NB];
__device__ int g_cnt[NB * SLOTMAX];
__device__ int g_list[NB * SLOTMAX * CELLS];   // (cell<<16)|n

// ---------------------------------------------------------------------------
// setup: 4 blocks (one per batch) x 512 threads.
// ---------------------------------------------------------------------------
__global__ __launch_bounds__(512) void setup_kernel(const void* __restrict__ ys_raw,
                                                    const void* __restrict__ xs_raw)
{
    const int b = blockIdx.x;
    const int tid = threadIdx.x;

    __shared__ int s_bad, s_ymin, s_ymax, s_xmin, s_xmax;
    __shared__ unsigned char s_mask[512];
    __shared__ short s_slot[512];
    __shared__ int s_cnt[512];
    __shared__ int s_ws[16];
    __shared__ int s_nH, s_nW, s_T;

    if (tid == 0) { s_bad = 0; s_ymin = 1 << 30; s_ymax = -1; s_xmin = 1 << 30; s_xmax = -1; }
    s_mask[tid] = 0;
    s_cnt[tid] = 0;
    __syncthreads();

    // dtype detect (int64 LE: odd 32-bit words all 0)
    {
        const int* yw = (const int*)ys_raw;
        const int* xw = (const int*)xs_raw;
        int bad = 0;
        for (int i = b * 2 * NP + 1 + 2 * tid; i < (b + 1) * 2 * NP; i += 1024)
            bad |= yw[i] | xw[i];
        bad = __reduce_or_sync(0xffffffffu, bad);
        if ((tid & 31) == 0 && bad) atomicOr(&s_bad, 1);
    }
    __syncthreads();
    const bool is64 = (s_bad == 0);

    int py[4], px[4];
#pragma unroll
    for (int j = 0; j < 4; j++) {
        const int idx = b * NP + tid + j * 512;
        if (is64) {
            py[j] = (int)((const long long*)ys_raw)[idx];
            px[j] = (int)((const long long*)xs_raw)[idx];
        } else {
            py[j] = ((const int*)ys_raw)[idx];
            px[j] = ((const int*)xs_raw)[idx];
        }
    }
    {
        int ymn = py[0], ymx = py[0], xmn = px[0], xmx = px[0];
#pragma unroll
        for (int j = 1; j < 4; j++) {
            ymn = min(ymn, py[j]); ymx = max(ymx, py[j]);
            xmn = min(xmn, px[j]); xmx = max(xmx, px[j]);
        }
        ymn = __reduce_min_sync(0xffffffffu, ymn);
        ymx = __reduce_max_sync(0xffffffffu, ymx);
        xmn = __reduce_min_sync(0xffffffffu, xmn);
        xmx = __reduce_max_sync(0xffffffffu, xmx);
        if ((tid & 31) == 0) {
            atomicMin(&s_ymin, ymn); atomicMax(&s_ymax, ymx);
            atomicMin(&s_xmin, xmn); atomicMax(&s_xmax, xmx);
        }
    }
    __syncthreads();
    if (tid == 0) {
        s_nH = (s_ymax - s_ymin + 1) / 6 + 1;
        s_nW = (s_xmax - s_xmin + 1) / 6 + 1;
        s_T = s_nH * s_nW;
    }
    __syncthreads();
    const int nH = s_nH, nW = s_nW, T = s_T;
    const int ymin = s_ymin, xmin = s_xmin;

    // shift + center occupancy (r%6: 1 -> none; 0 -> tile q-1; 2..5 -> tile q)
#pragma unroll
    for (int j = 0; j < 4; j++) {
        const int y = py[j] - ymin, x = px[j] - xmin;
        py[j] = y; px[j] = x;
        const int qy = y / 6, ry = y - 6 * qy;
        const int qx = x / 6, rx = x - 6 * qx;
        const int cy = (ry == 1) ? -1 : ((ry == 0) ? qy - 1 : qy);
        const int cx = (rx == 1) ? -1 : ((rx == 0) ? qx - 1 : qx);
        if (cy >= 0 && cx >= 0) s_mask[cy * nW + cx] = 1;
    }
    __syncthreads();

    // inclusive scan of flags over T (<=441)
    {
        const int w = tid >> 5, lane = tid & 31;
        const int f = (tid < T) ? (int)s_mask[tid] : 0;
        int v = f;
        for (int off = 1; off < 32; off <<= 1) {
            const int t = __shfl_up_sync(0xffffffffu, v, off);
            if (lane >= off) v += t;
        }
        if (lane == 31) s_ws[w] = v;
        __syncthreads();
        if (w == 0 && lane < 16) {
            int sv = s_ws[lane];
            for (int off = 1; off < 16; off <<= 1) {
                const int t = __shfl_up_sync(0xffffu, sv, off);
                if (lane >= off) sv += t;
            }
            s_ws[lane] = sv;
        }
        __syncthreads();
        const int pre = (w > 0) ? s_ws[w - 1] : 0;
        s_slot[tid] = (short)(f ? (pre + v - 1) : -1);
        if (tid == 0) g_selcnt[b] = s_ws[15];
    }
    __syncthreads();

    // scatter points into per-slot lists (each point covers <=2x2 windows)
#pragma unroll
    for (int j = 0; j < 4; j++) {
        const int y = py[j], x = px[j];
        const int n = tid + j * 512;
        const int ilo = (y > 8) ? (y - 3) / 6 : 0;
        int       ihi = y / 6;  if (ihi > nH - 1) ihi = nH - 1;
        const int jlo = (x > 8) ? (x - 3) / 6 : 0;
        int       jhi = x / 6;  if (jhi > nW - 1) jhi = nW - 1;
        for (int i = ilo; i <= ihi; i++)
            for (int jj = jlo; jj <= jhi; jj++) {
                const int slot = s_slot[i * nW + jj];
                if (slot >= 0) {
                    const int pos = atomicAdd(&s_cnt[slot], 1);
                    g_list[(b * SLOTMAX + slot) * CELLS + pos] =
                        ((y - i * 6) * TSZ + (x - jj * 6)) << 16 | n;
                }
            }
    }
    __syncthreads();
    g_cnt[b * SLOTMAX + tid] = s_cnt[tid];
}

// ---------------------------------------------------------------------------
// tiles: one block per (tile, 64-channel chunk). Zero+fill a dense [64][81]
// chunk in smem (coalesced gathers, conflict-free stride-81 STS), then emit
// as a pure aligned LDS.128 -> STG.128 stream. grid = K * NCHUNK.
// ---------------------------------------------------------------------------
__global__ __launch_bounds__(256, 8) void tiles_kernel(const float* __restrict__ features,
                                                       float* __restrict__ out,
                                                       int ns_count, int head)
{
    const int s     = blockIdx.x >> 3;          // tile
    const int chunk = blockIdx.x & (NCHUNK - 1);
    const int tid = threadIdx.x;

    __shared__ float sval[CHUNK_ELEMS + 8];     // +pad for alignment shift
    __shared__ short s_cell[CELLS], s_pn[CELLS];
    __shared__ int s_info[3];                   // b, local, cnt

    if (tid == 0) {
        const int c0 = g_selcnt[0], c1 = g_selcnt[1], c2 = g_selcnt[2];
        int b, local = s;
        if (s < c0)                { b = 0; }
        else if (s < c0 + c1)      { b = 1; local = s - c0; }
        else if (s < c0 + c1 + c2) { b = 2; local = s - c0 - c1; }
        else                       { b = 3; local = s - c0 - c1 - c2; }
        s_info[0] = b; s_info[1] = local;
        s_info[2] = g_cnt[b * SLOTMAX + local];
        if (ns_count > 0 && chunk == 0) out[s] = (float)b;   // f_ns
    }
    // zero staging buffer (float4, 16B-aligned)
    {
        const float4 z = make_float4(0.f, 0.f, 0.f, 0.f);
        for (int i = tid; i < (CHUNK_ELEMS + 8) / 4; i += 256)
            ((float4*)sval)[i] = z;
    }
    __syncthreads();
    const int b = s_info[0], local = s_info[1], cnt = s_info[2];
    if (tid < cnt) {
        const int e = g_list[(b * SLOTMAX + local) * CELLS + tid];
        s_cell[tid] = (short)(e >> 16);
        s_pn[tid]   = (short)(e & 0xffff);
    }
    __syncthreads();

    const float* __restrict__ fb = features + (size_t)b * (NP * NC) + chunk * CHUNK;
    const int ofs = (4 - head) & 3;             // (ofs+head) % 4 == 0

    // fill: each point contributes CHUNK consecutive channels (coalesced LDG);
    // STS stride-81 words (81 odd -> conflict-free)
    for (int i = tid; i < cnt * CHUNK; i += 256) {
        const int p = i >> 6, c = i & (CHUNK - 1);
        sval[ofs + c * CELLS + (int)s_cell[p]] = __ldg(fb + (int)s_pn[p] * NC + c);
    }
    __syncthreads();

    // emit: pure aligned copy
    float* __restrict__ oc = out + (size_t)ns_count + (size_t)s * TILE_ELEMS
                                 + (size_t)chunk * CHUNK_ELEMS;
    const int nb4  = (CHUNK_ELEMS - head) >> 2;
    const int tail = (CHUNK_ELEMS - head) & 3;

    for (int j = tid; j < head; j += 256)
        oc[j] = sval[ofs + j];
    for (int k = tid; k < nb4; k += 256) {
        const int j = head + (k << 2);
        const float4 v = *(const float4*)(sval + ofs + j);
        __stcs((float4*)(oc + j), v);
    }
    for (int k = tid; k < tail; k += 256) {
        const int j = head + (nb4 << 2) + k;
        oc[j] = sval[ofs + j];
    }
}

// ---------------------------------------------------------------------------
extern "C" void kernel_launch(void* const* d_in, const int* in_sizes, int n_in,
                              void* d_out, int out_size)
{
    int fi = 0;
    for (int i = 0; i < n_in; i++)
        if (in_sizes[i] == NB * NP * NC) fi = i;
    const float* features = (const float*)d_in[fi];
    const void* ys = nullptr;
    const void* xs = nullptr;
    for (int i = 0; i < n_in; i++) {
        if (i == fi) continue;
        if (!ys) ys = d_in[i];
        else if (!xs) xs = d_in[i];
    }

    setup_kernel<<<NB, 512>>>(ys, xs);

    int K, ns_count;
    if (out_size % (TILE_ELEMS + 1) == 0) {
        K = out_size / (TILE_ELEMS + 1);
        ns_count = K;
    } else {
        K = out_size / TILE_ELEMS;
        ns_count = 0;
    }
    if (K <= 0) return;
    if (K > NB * SLOTMAX) K = NB * SLOTMAX;

    const int head = (4 - (ns_count & 3)) & 3;
    tiles_kernel<<<K * NCHUNK, 256>>>(features, (float*)d_out, ns_count, head);
}